// round 15
// baseline (speedup 1.0000x reference)
#include <cuda_runtime.h>
#include <cuda_fp16.h>
#include <math.h>
#include <stdint.h>

// Problem constants
#define BB   4
#define SS   2048
#define DIM  2048
#define NH   16
#define HD   128
#define TOK  (BB * SS)          // 8192
#define EPSF 1e-6f

#define NX (TOK * DIM)          // 16777216
#define NW (DIM * DIM)          // 4194304

// Scratch (device globals: allocation-free)
__device__ float  g_qf[(size_t)TOK * DIM];
__device__ float  g_kf[(size_t)TOK * DIM];
__device__ __half g_xh[(size_t)TOK * DIM];
__device__ __half g_qh[(size_t)TOK * DIM];
__device__ __half g_kh[(size_t)TOK * DIM];
__device__ __half g_vh[(size_t)TOK * DIM];
__device__ __half g_oh[(size_t)TOK * DIM];
__device__ __half g_wqh[(size_t)DIM * DIM];
__device__ __half g_wkh[(size_t)DIM * DIM];
__device__ __half g_wvh[(size_t)DIM * DIM];
__device__ __half g_woh[(size_t)DIM * DIM];

// ---------------------------------------------------------------------------
// Common helpers
// ---------------------------------------------------------------------------
__device__ __forceinline__ uint32_t f2h2(float a, float b) {
    __half2 h = __floats2half2_rn(a, b);
    return *(uint32_t*)&h;
}

__device__ __forceinline__ uint2 f4h(float4 v) {
    return make_uint2(f2h2(v.x, v.y), f2h2(v.z, v.w));
}

__device__ __forceinline__ void mma_f16(float c[4], uint32_t a0, uint32_t a1,
                                        uint32_t a2, uint32_t a3,
                                        uint32_t b0, uint32_t b1) {
    asm volatile(
        "mma.sync.aligned.m16n8k16.row.col.f32.f16.f16.f32 "
        "{%0,%1,%2,%3}, {%4,%5,%6,%7}, {%8,%9}, {%0,%1,%2,%3};"
        : "+f"(c[0]), "+f"(c[1]), "+f"(c[2]), "+f"(c[3])
        : "r"(a0), "r"(a1), "r"(a2), "r"(a3), "r"(b0), "r"(b1));
}

// ---------------------------------------------------------------------------
// fp32 -> fp16 convert, all 5 tensors in ONE launch (flat offset select)
// total elems = NX + 4*NW; 4 per thread.
// ---------------------------------------------------------------------------
__global__ __launch_bounds__(256) void f2h_all(const float* __restrict__ x,
                                               const float* __restrict__ wq,
                                               const float* __restrict__ wk,
                                               const float* __restrict__ wv,
                                               const float* __restrict__ wo,
                                               __half* __restrict__ xh,
                                               __half* __restrict__ wqh,
                                               __half* __restrict__ wkh,
                                               __half* __restrict__ wvh,
                                               __half* __restrict__ woh)
{
    long i = ((long)blockIdx.x * 256 + threadIdx.x) * 4;
    const float* s;
    __half* d;
    long off;
    if (i < (long)NX) {
        s = x; d = xh; off = i;
    } else {
        long j = i - (long)NX;
        int t = (int)(j / NW);
        off = j - (long)t * NW;
        s = (t == 0) ? wq : (t == 1) ? wk : (t == 2) ? wv : wo;
        d = (t == 0) ? wqh : (t == 1) ? wkh : (t == 2) ? wvh : woh;
    }
    float4 v = *(const float4*)(s + off);
    *(uint2*)(d + off) = f4h(v);
}

// ---------------------------------------------------------------------------
// FP16 tensor-core GEMM (NT): C[m][n] = sum_k A[m][k] * B[n][k]
// R11-proven mainloop; multi-B dispatch (sel = blockIdx.x>>3).  (unchanged R13)
// ---------------------------------------------------------------------------
#define TBM 128
#define TBN 256
#define TBK 32
#define AST2 20   // half2 per row

#define GEMM_SMEM_WORDS (2 * (TBM + TBN) * AST2)   // 60 KB

__global__ __launch_bounds__(256) void gemm_h(const __half* __restrict__ A,
                                              const __half* __restrict__ B0,
                                              const __half* __restrict__ B1,
                                              const __half* __restrict__ B2,
                                              void* __restrict__ C0,
                                              void* __restrict__ C1,
                                              void* __restrict__ C2,
                                              int hout_mask, int M, int N, int K)
{
    extern __shared__ uint32_t smw[];
    uint32_t* As[2] = { smw, smw + TBM * AST2 };
    uint32_t* Bs[2] = { smw + 2 * TBM * AST2, smw + 2 * TBM * AST2 + TBN * AST2 };

    const int sel = blockIdx.x >> 3;
    const __half* B = (sel == 0) ? B0 : ((sel == 1) ? B1 : B2);
    void* Cv = (sel == 0) ? C0 : ((sel == 1) ? C1 : C2);
    const int hout = (hout_mask >> sel) & 1;

    const int bm = blockIdx.y * TBM;
    const int bn = (blockIdx.x & 7) * TBN;
    const int tid = threadIdx.x;
    const int warp = tid >> 5;
    const int lane = tid & 31;
    const int g = lane >> 2;
    const int cth = lane & 3;
    const int wm = warp & 1;
    const int wn = warp >> 1;

    const int ar = tid >> 2;             // 0..63
    const int ac = (tid & 3) * 8;        // half col
    const int ah = (tid & 3) * 4;        // half2 col

    float acc[4][8][4];
#pragma unroll
    for (int mi = 0; mi < 4; mi++)
#pragma unroll
        for (int ni = 0; ni < 8; ni++)
#pragma unroll
            for (int e = 0; e < 4; e++) acc[mi][ni][e] = 0.f;

    const int ntiles = K / TBK;   // 64

    uint4 ra[2], rb[4];
#pragma unroll
    for (int p = 0; p < 2; p++)
        ra[p] = *(const uint4*)(A + (size_t)(bm + ar + 64 * p) * K + ac);
#pragma unroll
    for (int p = 0; p < 4; p++)
        rb[p] = *(const uint4*)(B + (size_t)(bn + ar + 64 * p) * K + ac);
#pragma unroll
    for (int p = 0; p < 2; p++)
        *(uint4*)(As[0] + (ar + 64 * p) * AST2 + ah) = ra[p];
#pragma unroll
    for (int p = 0; p < 4; p++)
        *(uint4*)(Bs[0] + (ar + 64 * p) * AST2 + ah) = rb[p];
    __syncthreads();

    for (int t = 0; t < ntiles; t++) {
        if (t + 1 < ntiles) {
            const int off = (t + 1) * TBK + ac;
#pragma unroll
            for (int p = 0; p < 2; p++)
                ra[p] = *(const uint4*)(A + (size_t)(bm + ar + 64 * p) * K + off);
#pragma unroll
            for (int p = 0; p < 4; p++)
                rb[p] = *(const uint4*)(B + (size_t)(bn + ar + 64 * p) * K + off);
        }

        const uint32_t* as = As[t & 1];
        const uint32_t* bs = Bs[t & 1];

#pragma unroll
        for (int kch = 0; kch < 2; kch++) {
            const int kb = kch * 8;
            uint32_t a[4][4], b[8][2];
#pragma unroll
            for (int mi = 0; mi < 4; mi++) {
                const int rb0 = wm * 64 + mi * 16 + g;
                a[mi][0] = as[rb0 * AST2 + kb + cth];
                a[mi][1] = as[(rb0 + 8) * AST2 + kb + cth];
                a[mi][2] = as[rb0 * AST2 + kb + cth + 4];
                a[mi][3] = as[(rb0 + 8) * AST2 + kb + cth + 4];
            }
#pragma unroll
            for (int ni = 0; ni < 8; ni++) {
                const int cb = wn * 64 + ni * 8 + g;
                b[ni][0] = bs[cb * AST2 + kb + cth];
                b[ni][1] = bs[cb * AST2 + kb + cth + 4];
            }
#pragma unroll
            for (int mi = 0; mi < 4; mi++)
#pragma unroll
                for (int ni = 0; ni < 8; ni++)
                    mma_f16(acc[mi][ni], a[mi][0], a[mi][1], a[mi][2], a[mi][3],
                            b[ni][0], b[ni][1]);
        }

        if (t + 1 < ntiles) {
            uint32_t* asn = As[(t + 1) & 1];
            uint32_t* bsn = Bs[(t + 1) & 1];
#pragma unroll
            for (int p = 0; p < 2; p++)
                *(uint4*)(asn + (ar + 64 * p) * AST2 + ah) = ra[p];
#pragma unroll
            for (int p = 0; p < 4; p++)
                *(uint4*)(bsn + (ar + 64 * p) * AST2 + ah) = rb[p];
            __syncthreads();
        }
    }

    // Epilogue
#pragma unroll
    for (int mi = 0; mi < 4; mi++) {
        const int r0 = bm + wm * 64 + mi * 16 + g;
#pragma unroll
        for (int ni = 0; ni < 8; ni++) {
            const int col = bn + wn * 64 + ni * 8 + cth * 2;
            if (hout) {
                __half* C = (__half*)Cv;
                *(uint32_t*)(C + (size_t)r0 * N + col) = f2h2(acc[mi][ni][0], acc[mi][ni][1]);
                *(uint32_t*)(C + (size_t)(r0 + 8) * N + col) = f2h2(acc[mi][ni][2], acc[mi][ni][3]);
            } else {
                float* C = (float*)Cv;
                *(float2*)(C + (size_t)r0 * N + col) = make_float2(acc[mi][ni][0], acc[mi][ni][1]);
                *(float2*)(C + (size_t)(r0 + 8) * N + col) = make_float2(acc[mi][ni][2], acc[mi][ni][3]);
            }
        }
    }
}

// ---------------------------------------------------------------------------
// Fused per-head RMSNorm + RoPE, warp-per-(token,head), float4 loads.
// (unchanged R11)
// ---------------------------------------------------------------------------
__global__ __launch_bounds__(256) void rmsnorm_rope_v2(const float* __restrict__ qsrc,
                                                       const float* __restrict__ ksrc,
                                                       __half* __restrict__ qdst,
                                                       __half* __restrict__ kdst,
                                                       const float* __restrict__ qw,
                                                       const float* __restrict__ kw,
                                                       const float* __restrict__ cos_t,
                                                       const float* __restrict__ sin_t)
{
    const int wid = threadIdx.x >> 5;
    const int lane = threadIdx.x & 31;
    const int gidx = blockIdx.x * 8 + wid;    // 0..TOK*NH-1
    const int token = gidx >> 4;              // / NH
    const int h = gidx & 15;
    const int s = token & (SS - 1);
    const int d = lane * 4;

    const float* src = blockIdx.z ? ksrc : qsrc;
    __half* dst = blockIdx.z ? kdst : qdst;
    const float* w = blockIdx.z ? kw : qw;
    const float oscale = blockIdx.z ? 1.0f : 0.08838834764831845f;

    const size_t off = (size_t)token * DIM + h * HD + d;
    float4 v = *(const float4*)(src + off);

    float sq = v.x * v.x + v.y * v.y + v.z * v.z + v.w * v.w;
#pragma unroll
    for (int o = 16; o > 0; o >>= 1)
        sq += __shfl_xor_sync(0xffffffffu, sq, o);

    const float rms = rsqrtf(sq * (1.0f / HD) + EPSF);
    const float4 wv = *(const float4*)(w + d);
    float4 xn;
    xn.x = v.x * rms * wv.x;
    xn.y = v.y * rms * wv.y;
    xn.z = v.z * rms * wv.z;
    xn.w = v.w * rms * wv.w;

    float4 pr;
    pr.x = __shfl_xor_sync(0xffffffffu, xn.x, 16);
    pr.y = __shfl_xor_sync(0xffffffffu, xn.y, 16);
    pr.z = __shfl_xor_sync(0xffffffffu, xn.z, 16);
    pr.w = __shfl_xor_sync(0xffffffffu, xn.w, 16);
    const float sgn = (lane < 16) ? -1.0f : 1.0f;

    const float4 cv = *(const float4*)(cos_t + s * HD + d);
    const float4 sv = *(const float4*)(sin_t + s * HD + d);

    float o0 = (xn.x * cv.x + sgn * pr.x * sv.x) * oscale;
    float o1 = (xn.y * cv.y + sgn * pr.y * sv.y) * oscale;
    float o2 = (xn.z * cv.z + sgn * pr.z * sv.z) * oscale;
    float o3 = (xn.w * cv.w + sgn * pr.w * sv.w) * oscale;

    *(uint2*)(dst + off) = make_uint2(f2h2(o0, o1), f2h2(o2, o3));
}

// ---------------------------------------------------------------------------
// Causal flash attention, fp16 in/out, m16n8k16, double-buffered K/V with
// register prefetch (one __syncthreads per KV-tile, gmem latency hidden).
// BQ=128, BK=64, HD=128. 8 warps; warp w owns q-rows w*16..+15.
// ---------------------------------------------------------------------------
#define FBQ 128
#define FBK 64
#define QS2 68   // half2 per Q row
#define KS2 68   // half2 per K row
#define VT2 36   // half2 per Vt row (keys)
#define PS2 36   // half2 per P row

#define KBUF_WORDS (FBK * KS2)   // 4352
#define VBUF_WORDS (HD * VT2)    // 4608
#define FLASH_SMEM_WORDS (FBQ * QS2 + 2 * KBUF_WORDS + 2 * VBUF_WORDS + FBQ * PS2)

__global__ __launch_bounds__(256) void flash_f16(const __half* __restrict__ q,
                                                 const __half* __restrict__ k,
                                                 const __half* __restrict__ v,
                                                 __half* __restrict__ o)
{
    extern __shared__ uint32_t smh[];
    uint32_t* Qs2 = smh;                           // 128 x 68
    uint32_t* Kb[2] = { Qs2 + FBQ * QS2, Qs2 + FBQ * QS2 + KBUF_WORDS };
    uint32_t* Vb[2] = { Kb[1] + KBUF_WORDS, Kb[1] + KBUF_WORDS + VBUF_WORDS };
    uint32_t* Ps2 = Vb[1] + VBUF_WORDS;            // 128 x 36

    const int q0 = blockIdx.x * FBQ;
    const int bh = blockIdx.y;
    const int b = bh >> 4;
    const int h = bh & 15;
    const size_t base = (size_t)b * SS * DIM + (size_t)h * HD;

    const int tid = threadIdx.x;
    const int w = tid >> 5;
    const int lane = tid & 31;
    const int g = lane >> 2;
    const int cth = lane & 3;

    // loader mappings (per thread, fixed)
    const int lkr = tid >> 4;            // K row 0..15 (+16p)
    const int lkc = tid & 15;            // K col (x8 halves)
    const int lvkey = tid & 63;          // V key
    const int lvhd = (tid >> 6) * 8;     // V hd8 base (+32p)

    // ---- Load Q tile (pure half copy) ----
#pragma unroll
    for (int p = 0; p < 8; p++) {
        int idx = tid + p * 256;
        int r = idx >> 4;
        int c = idx & 15;
        uint4 u = *(const uint4*)(q + base + (size_t)(q0 + r) * DIM + c * 8);
        *(uint4*)(Qs2 + r * QS2 + c * 4) = u;
    }

    const int nkb = q0 / FBK + 2;

    // ---- prologue: tile 0 -> buf 0 ----
    {
        uint4 kr[4], vr[4];
#pragma unroll
        for (int p = 0; p < 4; p++)
            kr[p] = *(const uint4*)(k + base + (size_t)(lkr + 16 * p) * DIM + lkc * 8);
#pragma unroll
        for (int p = 0; p < 4; p++)
            vr[p] = *(const uint4*)(v + base + (size_t)lvkey * DIM + lvhd + 32 * p);
#pragma unroll
        for (int p = 0; p < 4; p++)
            *(uint4*)(Kb[0] + (lkr + 16 * p) * KS2 + lkc * 4) = kr[p];
        __half* VtH0 = (__half*)Vb[0];
#pragma unroll
        for (int p = 0; p < 4; p++) {
            __half hv[8];
            *(uint4*)hv = vr[p];
#pragma unroll
            for (int j = 0; j < 8; j++)
                VtH0[(lvhd + 32 * p + j) * (2 * VT2) + lvkey] = hv[j];
        }
    }
    __syncthreads();

    float m0 = -INFINITY, m1 = -INFINITY, l0 = 0.f, l1 = 0.f;
    float acc[16][4];
#pragma unroll
    for (int nb = 0; nb < 16; nb++)
#pragma unroll
        for (int e = 0; e < 4; e++) acc[nb][e] = 0.f;

    const int rowg = q0 + w * 16 + g;
    uint32_t* Qw2 = Qs2 + (w * 16) * QS2;
    uint32_t* Pw2 = Ps2 + (w * 16) * PS2;

    for (int kb = 0; kb < nkb; kb++) {
        const int k0 = kb * FBK;
        const int buf = kb & 1;

        // ---- prefetch next tile into registers ----
        uint4 krn[4], vrn[4];
        const bool more = (kb + 1 < nkb);
        if (more) {
            const int kn0 = (kb + 1) * FBK;
#pragma unroll
            for (int p = 0; p < 4; p++)
                krn[p] = *(const uint4*)(k + base + (size_t)(kn0 + lkr + 16 * p) * DIM + lkc * 8);
#pragma unroll
            for (int p = 0; p < 4; p++)
                vrn[p] = *(const uint4*)(v + base + (size_t)(kn0 + lvkey) * DIM + lvhd + 32 * p);
        }

        // ---- compute on buf (skip fully-masked tiles for this warp) ----
        if (k0 <= q0 + w * 16 + 15) {
            const uint32_t* Ks2 = Kb[buf];
            const uint32_t* Vt2 = Vb[buf];

            float c[8][4];
#pragma unroll
            for (int nb = 0; nb < 8; nb++)
#pragma unroll
                for (int e = 0; e < 4; e++) c[nb][e] = 0.f;

#pragma unroll 2
            for (int kc = 0; kc < 8; kc++) {
                const int kh = kc * 8;
                uint32_t a0 = Qw2[g * QS2 + kh + cth];
                uint32_t a1 = Qw2[(g + 8) * QS2 + kh + cth];
                uint32_t a2 = Qw2[g * QS2 + kh + cth + 4];
                uint32_t a3 = Qw2[(g + 8) * QS2 + kh + cth + 4];
#pragma unroll
                for (int nb = 0; nb < 8; nb++) {
                    const int n = nb * 8 + g;
                    uint32_t b0 = Ks2[n * KS2 + kh + cth];
                    uint32_t b1 = Ks2[n * KS2 + kh + cth + 4];
                    mma_f16(c[nb], a0, a1, a2, a3, b0, b1);
                }
            }

            if (k0 + FBK - 1 > rowg) {
#pragma unroll
                for (int nb = 0; nb < 8; nb++) {
                    const int col = k0 + nb * 8 + 2 * cth;
                    if (col > rowg)         c[nb][0] = -INFINITY;
                    if (col + 1 > rowg)     c[nb][1] = -INFINITY;
                    if (col > rowg + 8)     c[nb][2] = -INFINITY;
                    if (col + 1 > rowg + 8) c[nb][3] = -INFINITY;
                }
            }

            float mx0 = -INFINITY, mx1 = -INFINITY;
#pragma unroll
            for (int nb = 0; nb < 8; nb++) {
                mx0 = fmaxf(mx0, fmaxf(c[nb][0], c[nb][1]));
                mx1 = fmaxf(mx1, fmaxf(c[nb][2], c[nb][3]));
            }
            mx0 = fmaxf(mx0, __shfl_xor_sync(0xffffffffu, mx0, 1));
            mx0 = fmaxf(mx0, __shfl_xor_sync(0xffffffffu, mx0, 2));
            mx1 = fmaxf(mx1, __shfl_xor_sync(0xffffffffu, mx1, 1));
            mx1 = fmaxf(mx1, __shfl_xor_sync(0xffffffffu, mx1, 2));

            const float mn0 = fmaxf(m0, mx0);
            const float mn1 = fmaxf(m1, mx1);
            float rs0 = 0.f, rs1 = 0.f;
#pragma unroll
            for (int nb = 0; nb < 8; nb++) {
                c[nb][0] = __expf(c[nb][0] - mn0);
                c[nb][1] = __expf(c[nb][1] - mn0);
                c[nb][2] = __expf(c[nb][2] - mn1);
                c[nb][3] = __expf(c[nb][3] - mn1);
                rs0 += c[nb][0] + c[nb][1];
                rs1 += c[nb][2] + c[nb][3];
            }
            rs0 += __shfl_xor_sync(0xffffffffu, rs0, 1);
            rs0 += __shfl_xor_sync(0xffffffffu, rs0, 2);
            rs1 += __shfl_xor_sync(0xffffffffu, rs1, 1);
            rs1 += __shfl_xor_sync(0xffffffffu, rs1, 2);

            const float al0 = __expf(m0 - mn0);
            const float al1 = __expf(m1 - mn1);
            l0 = l0 * al0 + rs0;
            l1 = l1 * al1 + rs1;
            m0 = mn0;
            m1 = mn1;

#pragma unroll
            for (int nb = 0; nb < 16; nb++) {
                acc[nb][0] *= al0; acc[nb][1] *= al0;
                acc[nb][2] *= al1; acc[nb][3] *= al1;
            }

#pragma unroll
            for (int nb = 0; nb < 8; nb++) {
                Pw2[g * PS2 + nb * 4 + cth]       = f2h2(c[nb][0], c[nb][1]);
                Pw2[(g + 8) * PS2 + nb * 4 + cth] = f2h2(c[nb][2], c[nb][3]);
            }
            __syncwarp();

#pragma unroll
            for (int kc = 0; kc < 4; kc++) {
                const int kh = kc * 8;
                uint32_t a0 = Pw2[g * PS2 + kh + cth];
                uint32_t a1 = Pw2[(g + 8) * PS2 + kh + cth];
                uint32_t a2 = Pw2[g * PS2 + kh + cth + 4];
                uint32_t a3 = Pw2[(g + 8) * PS2 + kh + cth + 4];
#pragma unroll
                for (int nb = 0; nb < 16; nb++) {
                    const int n = nb * 8 + g;
                    uint32_t b0 = Vt2[n * VT2 + kh + cth];
                    uint32_t b1 = Vt2[n * VT2 + kh + cth + 4];
                    mma_f16(acc[nb], a0, a1, a2, a3, b0, b1);
                }
            }
            __syncwarp();
        }

        // ---- stage next tile into buf^1, then one barrier ----
        if (more) {
            uint32_t* Kn = Kb[buf ^ 1];
            __half* VtHn = (__half*)Vb[buf ^ 1];
#pragma unroll
            for (int p = 0; p < 4; p++)
                *(uint4*)(Kn + (lkr + 16 * p) * KS2 + lkc * 4) = krn[p];
#pragma unroll
            for (int p = 0; p < 4; p++) {
                __half hv[8];
                *(uint4*)hv = vrn[p];
#pragma unroll
                for (int j = 0; j < 8; j++)
                    VtHn[(lvhd + 32 * p + j) * (2 * VT2) + lvkey] = hv[j];
            }
            __syncthreads();
        }
    }

    // ---- epilogue: half out ----
    const float il0 = 1.0f / l0;
    const float il1 = 1.0f / l1;
    const size_t r0 = (size_t)rowg;
    const size_t r1 = (size_t)(rowg + 8);
#pragma unroll
    for (int nb = 0; nb < 16; nb++) {
        const int col = nb * 8 + 2 * cth;
        *(uint32_t*)(o + base + r0 * DIM + col) = f2h2(acc[nb][0] * il0, acc[nb][1] * il0);
        *(uint32_t*)(o + base + r1 * DIM + col) = f2h2(acc[nb][2] * il1, acc[nb][3] * il1);
    }
}

// ---------------------------------------------------------------------------
// Launch
// Inputs: 0=x 1=rope_cos 2=rope_sin 3=attn_mask 4=wq 5=wk 6=wv 7=wo
//         8=q_norm_w 9=k_norm_w
// ---------------------------------------------------------------------------
extern "C" void kernel_launch(void* const* d_in, const int* in_sizes, int n_in,
                              void* d_out, int out_size)
{
    const float* x       = (const float*)d_in[0];
    const float* rope_c  = (const float*)d_in[1];
    const float* rope_s  = (const float*)d_in[2];
    const float* wq      = (const float*)d_in[4];
    const float* wk      = (const float*)d_in[5];
    const float* wv      = (const float*)d_in[6];
    const float* wo      = (const float*)d_in[7];
    const float* qnw     = (const float*)d_in[8];
    const float* knw     = (const float*)d_in[9];
    float* out = (float*)d_out;

    float *qf, *kf;
    __half *xh, *qh, *kh, *vh, *oh, *wqh, *wkh, *wvh, *woh;
    cudaGetSymbolAddress((void**)&qf, g_qf);
    cudaGetSymbolAddress((void**)&kf, g_kf);
    cudaGetSymbolAddress((void**)&xh, g_xh);
    cudaGetSymbolAddress((void**)&qh, g_qh);
    cudaGetSymbolAddress((void**)&kh, g_kh);
    cudaGetSymbolAddress((void**)&vh, g_vh);
    cudaGetSymbolAddress((void**)&oh, g_oh);
    cudaGetSymbolAddress((void**)&wqh, g_wqh);
    cudaGetSymbolAddress((void**)&wkh, g_wkh);
    cudaGetSymbolAddress((void**)&wvh, g_wvh);
    cudaGetSymbolAddress((void**)&woh, g_woh);

    // Convert all 5 inputs to fp16 in ONE launch
    const long NTOT = (long)NX + 4L * NW;          // 33554432
    f2h_all<<<(int)(NTOT / 4 / 256), 256>>>(x, wq, wk, wv, wo,
                                            xh, wqh, wkh, wvh, woh);

    const int gemm_smem = GEMM_SMEM_WORDS * sizeof(uint32_t);  // 60 KB
    cudaFuncSetAttribute(gemm_h, cudaFuncAttributeMaxDynamicSharedMemorySize,
                         gemm_smem);

    // Fused QKV launch: sel 0->q(f32), 1->k(f32), 2->v(half). 1536 CTAs.
    dim3 qkvgrid(3 * DIM / TBN, TOK / TBM);  // (24, 64)
    gemm_h<<<qkvgrid, 256, gemm_smem>>>(xh, wqh, wkh, wvh, qf, kf, vh,
                                        /*hout_mask=*/0b100, TOK, DIM, DIM);

    // warp-per-(token,head) rmsnorm+rope
    dim3 ngrid(TOK * NH / 8, 1, 2);
    rmsnorm_rope_v2<<<ngrid, 256>>>(qf, kf, qh, kh, qnw, knw, rope_c, rope_s);

    const int flash_smem = FLASH_SMEM_WORDS * sizeof(uint32_t);  // ~125 KB
    cudaFuncSetAttribute(flash_f16, cudaFuncAttributeMaxDynamicSharedMemorySize,
                         flash_smem);
    dim3 fgrid(SS / FBQ, BB * NH);  // (16, 64)
    flash_f16<<<fgrid, 256, flash_smem>>>(qh, kh, vh, oh);

    // Output projection (single B path)
    dim3 ogrid(DIM / TBN, TOK / TBM);  // (8, 64)
    gemm_h<<<ogrid, 256, gemm_smem>>>(oh, woh, woh, woh, out, out, out,
                                      /*hout_mask=*/0, TOK, DIM, DIM);
}

// round 17
// speedup vs baseline: 1.0490x; 1.0490x over previous
#include <cuda_runtime.h>
#include <cuda_fp16.h>
#include <math.h>
#include <stdint.h>

// Problem constants
#define BB   4
#define SS   2048
#define DIM  2048
#define NH   16
#define HD   128
#define TOK  (BB * SS)          // 8192
#define EPSF 1e-6f

#define NX (TOK * DIM)          // 16777216
#define NW (DIM * DIM)          // 4194304

// Scratch (device globals: allocation-free)
__device__ float  g_qf[(size_t)TOK * DIM];
__device__ float  g_kf[(size_t)TOK * DIM];
__device__ __half g_xh[(size_t)TOK * DIM];
__device__ __half g_qh[(size_t)TOK * DIM];
__device__ __half g_kh[(size_t)TOK * DIM];
__device__ __half g_vh[(size_t)TOK * DIM];
__device__ __half g_oh[(size_t)TOK * DIM];
__device__ __half g_wqh[(size_t)DIM * DIM];
__device__ __half g_wkh[(size_t)DIM * DIM];
__device__ __half g_wvh[(size_t)DIM * DIM];
__device__ __half g_woh[(size_t)DIM * DIM];

// ---------------------------------------------------------------------------
// Common helpers
// ---------------------------------------------------------------------------
__device__ __forceinline__ uint32_t f2h2(float a, float b) {
    __half2 h = __floats2half2_rn(a, b);
    return *(uint32_t*)&h;
}

__device__ __forceinline__ uint2 f4h(float4 v) {
    return make_uint2(f2h2(v.x, v.y), f2h2(v.z, v.w));
}

__device__ __forceinline__ void mma_f16(float c[4], uint32_t a0, uint32_t a1,
                                        uint32_t a2, uint32_t a3,
                                        uint32_t b0, uint32_t b1) {
    asm volatile(
        "mma.sync.aligned.m16n8k16.row.col.f32.f16.f16.f32 "
        "{%0,%1,%2,%3}, {%4,%5,%6,%7}, {%8,%9}, {%0,%1,%2,%3};"
        : "+f"(c[0]), "+f"(c[1]), "+f"(c[2]), "+f"(c[3])
        : "r"(a0), "r"(a1), "r"(a2), "r"(a3), "r"(b0), "r"(b1));
}

// ---------------------------------------------------------------------------
// fp32 -> fp16 convert, all 5 tensors in ONE launch (flat offset select)
// ---------------------------------------------------------------------------
__global__ __launch_bounds__(256) void f2h_all(const float* __restrict__ x,
                                               const float* __restrict__ wq,
                                               const float* __restrict__ wk,
                                               const float* __restrict__ wv,
                                               const float* __restrict__ wo,
                                               __half* __restrict__ xh,
                                               __half* __restrict__ wqh,
                                               __half* __restrict__ wkh,
                                               __half* __restrict__ wvh,
                                               __half* __restrict__ woh)
{
    long i = ((long)blockIdx.x * 256 + threadIdx.x) * 4;
    const float* s;
    __half* d;
    long off;
    if (i < (long)NX) {
        s = x; d = xh; off = i;
    } else {
        long j = i - (long)NX;
        int t = (int)(j / NW);
        off = j - (long)t * NW;
        s = (t == 0) ? wq : (t == 1) ? wk : (t == 2) ? wv : wo;
        d = (t == 0) ? wqh : (t == 1) ? wkh : (t == 2) ? wvh : woh;
    }
    float4 v = *(const float4*)(s + off);
    *(uint2*)(d + off) = f4h(v);
}

// ---------------------------------------------------------------------------
// FP16 tensor-core GEMM (NT): C[m][n] = sum_k A[m][k] * B[n][k]
// R11-proven mainloop; multi-B dispatch (sel = blockIdx.x>>3). (unchanged R13)
// ---------------------------------------------------------------------------
#define TBM 128
#define TBN 256
#define TBK 32
#define AST2 20   // half2 per row

#define GEMM_SMEM_WORDS (2 * (TBM + TBN) * AST2)   // 60 KB

__global__ __launch_bounds__(256) void gemm_h(const __half* __restrict__ A,
                                              const __half* __restrict__ B0,
                                              const __half* __restrict__ B1,
                                              const __half* __restrict__ B2,
                                              void* __restrict__ C0,
                                              void* __restrict__ C1,
                                              void* __restrict__ C2,
                                              int hout_mask, int M, int N, int K)
{
    extern __shared__ uint32_t smw[];
    uint32_t* As[2] = { smw, smw + TBM * AST2 };
    uint32_t* Bs[2] = { smw + 2 * TBM * AST2, smw + 2 * TBM * AST2 + TBN * AST2 };

    const int sel = blockIdx.x >> 3;
    const __half* B = (sel == 0) ? B0 : ((sel == 1) ? B1 : B2);
    void* Cv = (sel == 0) ? C0 : ((sel == 1) ? C1 : C2);
    const int hout = (hout_mask >> sel) & 1;

    const int bm = blockIdx.y * TBM;
    const int bn = (blockIdx.x & 7) * TBN;
    const int tid = threadIdx.x;
    const int warp = tid >> 5;
    const int lane = tid & 31;
    const int g = lane >> 2;
    const int cth = lane & 3;
    const int wm = warp & 1;
    const int wn = warp >> 1;

    const int ar = tid >> 2;             // 0..63
    const int ac = (tid & 3) * 8;        // half col
    const int ah = (tid & 3) * 4;        // half2 col

    float acc[4][8][4];
#pragma unroll
    for (int mi = 0; mi < 4; mi++)
#pragma unroll
        for (int ni = 0; ni < 8; ni++)
#pragma unroll
            for (int e = 0; e < 4; e++) acc[mi][ni][e] = 0.f;

    const int ntiles = K / TBK;   // 64

    uint4 ra[2], rb[4];
#pragma unroll
    for (int p = 0; p < 2; p++)
        ra[p] = *(const uint4*)(A + (size_t)(bm + ar + 64 * p) * K + ac);
#pragma unroll
    for (int p = 0; p < 4; p++)
        rb[p] = *(const uint4*)(B + (size_t)(bn + ar + 64 * p) * K + ac);
#pragma unroll
    for (int p = 0; p < 2; p++)
        *(uint4*)(As[0] + (ar + 64 * p) * AST2 + ah) = ra[p];
#pragma unroll
    for (int p = 0; p < 4; p++)
        *(uint4*)(Bs[0] + (ar + 64 * p) * AST2 + ah) = rb[p];
    __syncthreads();

    for (int t = 0; t < ntiles; t++) {
        if (t + 1 < ntiles) {
            const int off = (t + 1) * TBK + ac;
#pragma unroll
            for (int p = 0; p < 2; p++)
                ra[p] = *(const uint4*)(A + (size_t)(bm + ar + 64 * p) * K + off);
#pragma unroll
            for (int p = 0; p < 4; p++)
                rb[p] = *(const uint4*)(B + (size_t)(bn + ar + 64 * p) * K + off);
        }

        const uint32_t* as = As[t & 1];
        const uint32_t* bs = Bs[t & 1];

#pragma unroll
        for (int kch = 0; kch < 2; kch++) {
            const int kb = kch * 8;
            uint32_t a[4][4], b[8][2];
#pragma unroll
            for (int mi = 0; mi < 4; mi++) {
                const int rb0 = wm * 64 + mi * 16 + g;
                a[mi][0] = as[rb0 * AST2 + kb + cth];
                a[mi][1] = as[(rb0 + 8) * AST2 + kb + cth];
                a[mi][2] = as[rb0 * AST2 + kb + cth + 4];
                a[mi][3] = as[(rb0 + 8) * AST2 + kb + cth + 4];
            }
#pragma unroll
            for (int ni = 0; ni < 8; ni++) {
                const int cb = wn * 64 + ni * 8 + g;
                b[ni][0] = bs[cb * AST2 + kb + cth];
                b[ni][1] = bs[cb * AST2 + kb + cth + 4];
            }
#pragma unroll
            for (int mi = 0; mi < 4; mi++)
#pragma unroll
                for (int ni = 0; ni < 8; ni++)
                    mma_f16(acc[mi][ni], a[mi][0], a[mi][1], a[mi][2], a[mi][3],
                            b[ni][0], b[ni][1]);
        }

        if (t + 1 < ntiles) {
            uint32_t* asn = As[(t + 1) & 1];
            uint32_t* bsn = Bs[(t + 1) & 1];
#pragma unroll
            for (int p = 0; p < 2; p++)
                *(uint4*)(asn + (ar + 64 * p) * AST2 + ah) = ra[p];
#pragma unroll
            for (int p = 0; p < 4; p++)
                *(uint4*)(bsn + (ar + 64 * p) * AST2 + ah) = rb[p];
            __syncthreads();
        }
    }

    // Epilogue
#pragma unroll
    for (int mi = 0; mi < 4; mi++) {
        const int r0 = bm + wm * 64 + mi * 16 + g;
#pragma unroll
        for (int ni = 0; ni < 8; ni++) {
            const int col = bn + wn * 64 + ni * 8 + cth * 2;
            if (hout) {
                __half* C = (__half*)Cv;
                *(uint32_t*)(C + (size_t)r0 * N + col) = f2h2(acc[mi][ni][0], acc[mi][ni][1]);
                *(uint32_t*)(C + (size_t)(r0 + 8) * N + col) = f2h2(acc[mi][ni][2], acc[mi][ni][3]);
            } else {
                float* C = (float*)Cv;
                *(float2*)(C + (size_t)r0 * N + col) = make_float2(acc[mi][ni][0], acc[mi][ni][1]);
                *(float2*)(C + (size_t)(r0 + 8) * N + col) = make_float2(acc[mi][ni][2], acc[mi][ni][3]);
            }
        }
    }
}

// ---------------------------------------------------------------------------
// Fused per-head RMSNorm + RoPE, warp-per-(token,head), float4 loads.
// (unchanged R11)
// ---------------------------------------------------------------------------
__global__ __launch_bounds__(256) void rmsnorm_rope_v2(const float* __restrict__ qsrc,
                                                       const float* __restrict__ ksrc,
                                                       __half* __restrict__ qdst,
                                                       __half* __restrict__ kdst,
                                                       const float* __restrict__ qw,
                                                       const float* __restrict__ kw,
                                                       const float* __restrict__ cos_t,
                                                       const float* __restrict__ sin_t)
{
    const int wid = threadIdx.x >> 5;
    const int lane = threadIdx.x & 31;
    const int gidx = blockIdx.x * 8 + wid;    // 0..TOK*NH-1
    const int token = gidx >> 4;              // / NH
    const int h = gidx & 15;
    const int s = token & (SS - 1);
    const int d = lane * 4;

    const float* src = blockIdx.z ? ksrc : qsrc;
    __half* dst = blockIdx.z ? kdst : qdst;
    const float* w = blockIdx.z ? kw : qw;
    const float oscale = blockIdx.z ? 1.0f : 0.08838834764831845f;

    const size_t off = (size_t)token * DIM + h * HD + d;
    float4 v = *(const float4*)(src + off);

    float sq = v.x * v.x + v.y * v.y + v.z * v.z + v.w * v.w;
#pragma unroll
    for (int o = 16; o > 0; o >>= 1)
        sq += __shfl_xor_sync(0xffffffffu, sq, o);

    const float rms = rsqrtf(sq * (1.0f / HD) + EPSF);
    const float4 wv = *(const float4*)(w + d);
    float4 xn;
    xn.x = v.x * rms * wv.x;
    xn.y = v.y * rms * wv.y;
    xn.z = v.z * rms * wv.z;
    xn.w = v.w * rms * wv.w;

    float4 pr;
    pr.x = __shfl_xor_sync(0xffffffffu, xn.x, 16);
    pr.y = __shfl_xor_sync(0xffffffffu, xn.y, 16);
    pr.z = __shfl_xor_sync(0xffffffffu, xn.z, 16);
    pr.w = __shfl_xor_sync(0xffffffffu, xn.w, 16);
    const float sgn = (lane < 16) ? -1.0f : 1.0f;

    const float4 cv = *(const float4*)(cos_t + s * HD + d);
    const float4 sv = *(const float4*)(sin_t + s * HD + d);

    float o0 = (xn.x * cv.x + sgn * pr.x * sv.x) * oscale;
    float o1 = (xn.y * cv.y + sgn * pr.y * sv.y) * oscale;
    float o2 = (xn.z * cv.z + sgn * pr.z * sv.z) * oscale;
    float o3 = (xn.w * cv.w + sgn * pr.w * sv.w) * oscale;

    *(uint2*)(dst + off) = make_uint2(f2h2(o0, o1), f2h2(o2, o3));
}

// ---------------------------------------------------------------------------
// Causal flash attention, fp16 in / fp16 out, m16n8k16. R13 synchronous body,
// __launch_bounds__(256, 2): 128-reg cap -> 2 CTAs/SM (16 warps) for latency
// hiding (ncu: occ 12.3%, issue 28%, DRAM 2.9% -> latency-bound, not BW).
// BQ=128, BK=64, HD=128. 8 warps; warp w owns q-rows w*16..+15.
// ---------------------------------------------------------------------------
#define FBQ 128
#define FBK 64
#define QS2 68   // half2 per Q/K row
#define VT2 36   // half2 per Vt row (keys)
#define PS2 36   // half2 per P row

#define FLASH_SMEM_WORDS (FBQ * QS2 + FBK * QS2 + HD * VT2 + FBQ * PS2)

__global__ __launch_bounds__(256, 2) void flash_f16(const __half* __restrict__ q,
                                                    const __half* __restrict__ k,
                                                    const __half* __restrict__ v,
                                                    __half* __restrict__ o)
{
    extern __shared__ uint32_t smh[];
    uint32_t* Qs2 = smh;                       // 128 x 68
    uint32_t* Ks2 = Qs2 + FBQ * QS2;           // 64 x 68
    uint32_t* Vt2 = Ks2 + FBK * QS2;           // 128 x 36 (row = hd, col = key)
    uint32_t* Ps2 = Vt2 + HD * VT2;            // 128 x 36
    __half*  VtH = (__half*)Vt2;

    const int q0 = blockIdx.x * FBQ;
    const int bh = blockIdx.y;
    const int b = bh >> 4;
    const int h = bh & 15;
    const size_t base = (size_t)b * SS * DIM + (size_t)h * HD;

    const int tid = threadIdx.x;
    const int w = tid >> 5;
    const int lane = tid & 31;
    const int g = lane >> 2;
    const int cth = lane & 3;

#pragma unroll
    for (int p = 0; p < 8; p++) {
        int idx = tid + p * 256;
        int r = idx >> 4;
        int c = idx & 15;
        uint4 u = *(const uint4*)(q + base + (size_t)(q0 + r) * DIM + c * 8);
        *(uint4*)(Qs2 + r * QS2 + c * 4) = u;
    }

    float m0 = -INFINITY, m1 = -INFINITY, l0 = 0.f, l1 = 0.f;
    float acc[16][4];
#pragma unroll
    for (int nb = 0; nb < 16; nb++)
#pragma unroll
        for (int e = 0; e < 4; e++) acc[nb][e] = 0.f;

    const int rowg = q0 + w * 16 + g;
    uint32_t* Qw2 = Qs2 + (w * 16) * QS2;
    uint32_t* Pw2 = Ps2 + (w * 16) * PS2;

    const int nkb = q0 / FBK + 2;
    for (int kb = 0; kb < nkb; kb++) {
        const int k0 = kb * FBK;
        __syncthreads();

#pragma unroll
        for (int p = 0; p < 4; p++) {
            int idx = tid + p * 256;
            int r = idx >> 4;
            int c = idx & 15;
            uint4 u = *(const uint4*)(k + base + (size_t)(k0 + r) * DIM + c * 8);
            *(uint4*)(Ks2 + r * QS2 + c * 4) = u;
        }
#pragma unroll
        for (int p = 0; p < 4; p++) {
            int idx = tid + p * 256;
            int key = idx & 63;
            int hd8 = (idx >> 6) * 8;
            uint4 u = *(const uint4*)(v + base + (size_t)(k0 + key) * DIM + hd8);
            __half hv[8];
            *(uint4*)hv = u;
#pragma unroll
            for (int j = 0; j < 8; j++)
                VtH[(hd8 + j) * (2 * VT2) + key] = hv[j];
        }
        __syncthreads();

        if (k0 > q0 + w * 16 + 15) continue;

        float c[8][4];
#pragma unroll
        for (int nb = 0; nb < 8; nb++)
#pragma unroll
            for (int e = 0; e < 4; e++) c[nb][e] = 0.f;

#pragma unroll 2
        for (int kc = 0; kc < 8; kc++) {
            const int kh = kc * 8;
            uint32_t a0 = Qw2[g * QS2 + kh + cth];
            uint32_t a1 = Qw2[(g + 8) * QS2 + kh + cth];
            uint32_t a2 = Qw2[g * QS2 + kh + cth + 4];
            uint32_t a3 = Qw2[(g + 8) * QS2 + kh + cth + 4];
#pragma unroll
            for (int nb = 0; nb < 8; nb++) {
                const int n = nb * 8 + g;
                uint32_t b0 = Ks2[n * QS2 + kh + cth];
                uint32_t b1 = Ks2[n * QS2 + kh + cth + 4];
                mma_f16(c[nb], a0, a1, a2, a3, b0, b1);
            }
        }

        if (k0 + FBK - 1 > rowg) {
#pragma unroll
            for (int nb = 0; nb < 8; nb++) {
                const int col = k0 + nb * 8 + 2 * cth;
                if (col > rowg)         c[nb][0] = -INFINITY;
                if (col + 1 > rowg)     c[nb][1] = -INFINITY;
                if (col > rowg + 8)     c[nb][2] = -INFINITY;
                if (col + 1 > rowg + 8) c[nb][3] = -INFINITY;
            }
        }

        float mx0 = -INFINITY, mx1 = -INFINITY;
#pragma unroll
        for (int nb = 0; nb < 8; nb++) {
            mx0 = fmaxf(mx0, fmaxf(c[nb][0], c[nb][1]));
            mx1 = fmaxf(mx1, fmaxf(c[nb][2], c[nb][3]));
        }
        mx0 = fmaxf(mx0, __shfl_xor_sync(0xffffffffu, mx0, 1));
        mx0 = fmaxf(mx0, __shfl_xor_sync(0xffffffffu, mx0, 2));
        mx1 = fmaxf(mx1, __shfl_xor_sync(0xffffffffu, mx1, 1));
        mx1 = fmaxf(mx1, __shfl_xor_sync(0xffffffffu, mx1, 2));

        const float mn0 = fmaxf(m0, mx0);
        const float mn1 = fmaxf(m1, mx1);
        float rs0 = 0.f, rs1 = 0.f;
#pragma unroll
        for (int nb = 0; nb < 8; nb++) {
            c[nb][0] = __expf(c[nb][0] - mn0);
            c[nb][1] = __expf(c[nb][1] - mn0);
            c[nb][2] = __expf(c[nb][2] - mn1);
            c[nb][3] = __expf(c[nb][3] - mn1);
            rs0 += c[nb][0] + c[nb][1];
            rs1 += c[nb][2] + c[nb][3];
        }
        rs0 += __shfl_xor_sync(0xffffffffu, rs0, 1);
        rs0 += __shfl_xor_sync(0xffffffffu, rs0, 2);
        rs1 += __shfl_xor_sync(0xffffffffu, rs1, 1);
        rs1 += __shfl_xor_sync(0xffffffffu, rs1, 2);

        const float al0 = __expf(m0 - mn0);
        const float al1 = __expf(m1 - mn1);
        l0 = l0 * al0 + rs0;
        l1 = l1 * al1 + rs1;
        m0 = mn0;
        m1 = mn1;

#pragma unroll
        for (int nb = 0; nb < 16; nb++) {
            acc[nb][0] *= al0; acc[nb][1] *= al0;
            acc[nb][2] *= al1; acc[nb][3] *= al1;
        }

#pragma unroll
        for (int nb = 0; nb < 8; nb++) {
            Pw2[g * PS2 + nb * 4 + cth]       = f2h2(c[nb][0], c[nb][1]);
            Pw2[(g + 8) * PS2 + nb * 4 + cth] = f2h2(c[nb][2], c[nb][3]);
        }
        __syncwarp();

#pragma unroll
        for (int kc = 0; kc < 4; kc++) {
            const int kh = kc * 8;
            uint32_t a0 = Pw2[g * PS2 + kh + cth];
            uint32_t a1 = Pw2[(g + 8) * PS2 + kh + cth];
            uint32_t a2 = Pw2[g * PS2 + kh + cth + 4];
            uint32_t a3 = Pw2[(g + 8) * PS2 + kh + cth + 4];
#pragma unroll
            for (int nb = 0; nb < 16; nb++) {
                const int n = nb * 8 + g;
                uint32_t b0 = Vt2[n * VT2 + kh + cth];
                uint32_t b1 = Vt2[n * VT2 + kh + cth + 4];
                mma_f16(acc[nb], a0, a1, a2, a3, b0, b1);
            }
        }
        __syncwarp();
    }

    const float il0 = 1.0f / l0;
    const float il1 = 1.0f / l1;
    const size_t r0 = (size_t)rowg;
    const size_t r1 = (size_t)(rowg + 8);
#pragma unroll
    for (int nb = 0; nb < 16; nb++) {
        const int col = nb * 8 + 2 * cth;
        *(uint32_t*)(o + base + r0 * DIM + col) = f2h2(acc[nb][0] * il0, acc[nb][1] * il0);
        *(uint32_t*)(o + base + r1 * DIM + col) = f2h2(acc[nb][2] * il1, acc[nb][3] * il1);
    }
}

// ---------------------------------------------------------------------------
// Launch
// Inputs: 0=x 1=rope_cos 2=rope_sin 3=attn_mask 4=wq 5=wk 6=wv 7=wo
//         8=q_norm_w 9=k_norm_w
// ---------------------------------------------------------------------------
extern "C" void kernel_launch(void* const* d_in, const int* in_sizes, int n_in,
                              void* d_out, int out_size)
{
    const float* x       = (const float*)d_in[0];
    const float* rope_c  = (const float*)d_in[1];
    const float* rope_s  = (const float*)d_in[2];
    const float* wq      = (const float*)d_in[4];
    const float* wk      = (const float*)d_in[5];
    const float* wv      = (const float*)d_in[6];
    const float* wo      = (const float*)d_in[7];
    const float* qnw     = (const float*)d_in[8];
    const float* knw     = (const float*)d_in[9];
    float* out = (float*)d_out;

    float *qf, *kf;
    __half *xh, *qh, *kh, *vh, *oh, *wqh, *wkh, *wvh, *woh;
    cudaGetSymbolAddress((void**)&qf, g_qf);
    cudaGetSymbolAddress((void**)&kf, g_kf);
    cudaGetSymbolAddress((void**)&xh, g_xh);
    cudaGetSymbolAddress((void**)&qh, g_qh);
    cudaGetSymbolAddress((void**)&kh, g_kh);
    cudaGetSymbolAddress((void**)&vh, g_vh);
    cudaGetSymbolAddress((void**)&oh, g_oh);
    cudaGetSymbolAddress((void**)&wqh, g_wqh);
    cudaGetSymbolAddress((void**)&wkh, g_wkh);
    cudaGetSymbolAddress((void**)&wvh, g_wvh);
    cudaGetSymbolAddress((void**)&woh, g_woh);

    // Convert all 5 inputs to fp16 in ONE launch
    const long NTOT = (long)NX + 4L * NW;          // 33554432
    f2h_all<<<(int)(NTOT / 4 / 256), 256>>>(x, wq, wk, wv, wo,
                                            xh, wqh, wkh, wvh, woh);

    const int gemm_smem = GEMM_SMEM_WORDS * sizeof(uint32_t);  // 60 KB
    cudaFuncSetAttribute(gemm_h, cudaFuncAttributeMaxDynamicSharedMemorySize,
                         gemm_smem);

    // Fused QKV launch: sel 0->q(f32), 1->k(f32), 2->v(half). 1536 CTAs.
    dim3 qkvgrid(3 * DIM / TBN, TOK / TBM);  // (24, 64)
    gemm_h<<<qkvgrid, 256, gemm_smem>>>(xh, wqh, wkh, wvh, qf, kf, vh,
                                        /*hout_mask=*/0b100, TOK, DIM, DIM);

    // warp-per-(token,head) rmsnorm+rope
    dim3 ngrid(TOK * NH / 8, 1, 2);
    rmsnorm_rope_v2<<<ngrid, 256>>>(qf, kf, qh, kh, qnw, knw, rope_c, rope_s);

    const int flash_smem = FLASH_SMEM_WORDS * sizeof(uint32_t);  // ~87 KB
    cudaFuncSetAttribute(flash_f16, cudaFuncAttributeMaxDynamicSharedMemorySize,
                         flash_smem);
    dim3 fgrid(SS / FBQ, BB * NH);  // (16, 64)
    flash_f16<<<fgrid, 256, flash_smem>>>(qh, kh, vh, oh);

    // Output projection (single B path)
    dim3 ogrid(DIM / TBN, TOK / TBM);  // (8, 64)
    gemm_h<<<ogrid, 256, gemm_smem>>>(oh, woh, woh, woh, out, out, out,
                                      /*hout_mask=*/0, TOK, DIM, DIM);
}